// round 8
// baseline (speedup 1.0000x reference)
#include <cuda_runtime.h>
#include <cuda_fp16.h>
#include <cstddef>

#define GH 1024
#define GW 1024
#define GC 32
#define GHW (GH * GW)

#define BIN_SHIFT 3            // 8x8 cells per bin
#define NBX (GW >> BIN_SHIFT)  // 128
#define NBY (GH >> BIN_SHIFT)  // 128
#define NBINS (NBX * NBY)      // 16384
#define MAX_PTS 2000128

// 64 MB transposed fp16 params: [HW, C], 64B per cell.
__device__ __half g_params_h[(size_t)GHW * GC];
// Sorted point records: {x, y, bitcast(orig_idx), pad}. 32 MB.
__device__ float4 g_rec[MAX_PTS];
__device__ int g_hist[NBINS];
__device__ int g_ptr[NBINS];

// ---------------------------------------------------------------------------
// Kernel 1: transpose + convert. [C,HW] fp32 -> [HW,C] fp16. (unchanged)
// ---------------------------------------------------------------------------
__global__ void transpose_kernel(const float* __restrict__ in) {
    const int p = blockIdx.x * blockDim.x + threadIdx.x;
    float v[32];
#pragma unroll
    for (int c = 0; c < 32; c++) v[c] = __ldcs(in + (size_t)c * GHW + p);
    uint4* __restrict__ outv = (uint4*)(g_params_h + (size_t)p * GC);
#pragma unroll
    for (int q = 0; q < 4; q++) {
        union { __half2 h2[4]; uint4 u; } pack;
#pragma unroll
        for (int j = 0; j < 4; j++)
            pack.h2[j] = __floats2half2_rn(v[q * 8 + 2 * j], v[q * 8 + 2 * j + 1]);
        outv[q] = pack.u;
    }
}

__device__ __forceinline__ int bin_of(float x, float y) {
    const float ix = (x + 1.0f) * 0.5f * (float)(GW - 1);
    const float iy = (y + 1.0f) * 0.5f * (float)(GH - 1);
    int x0 = (int)floorf(ix); x0 = x0 < 0 ? 0 : (x0 > GW - 1 ? GW - 1 : x0);
    int y0 = (int)floorf(iy); y0 = y0 < 0 ? 0 : (y0 > GH - 1 ? GH - 1 : y0);
    return (y0 >> BIN_SHIFT) * NBX + (x0 >> BIN_SHIFT);
}

__global__ void zero_hist_kernel() {
    g_hist[blockIdx.x * blockDim.x + threadIdx.x] = 0;
}

__global__ void hist_kernel(const float* __restrict__ coord, int n) {
    const int p = blockIdx.x * blockDim.x + threadIdx.x;
    if (p >= n) return;
    const float2 xy = __ldcs(((const float2*)coord) + p);
    atomicAdd(&g_hist[bin_of(xy.x, xy.y)], 1);
}

// Exclusive prefix sum over 16384 bins, single block of 1024 threads.
__global__ void scan_kernel() {
    __shared__ int s[1024];
    const int t = threadIdx.x;
    int v[16]; int sum = 0;
#pragma unroll
    for (int i = 0; i < 16; i++) { v[i] = g_hist[t * 16 + i]; sum += v[i]; }
    s[t] = sum; __syncthreads();
    for (int off = 1; off < 1024; off <<= 1) {
        int add = (t >= off) ? s[t - off] : 0;
        __syncthreads();
        s[t] += add;
        __syncthreads();
    }
    int run = s[t] - sum;  // exclusive prefix of this thread's chunk
#pragma unroll
    for (int i = 0; i < 16; i++) { g_ptr[t * 16 + i] = run; run += v[i]; }
}

__global__ void scatter_kernel(const float* __restrict__ coord, int n) {
    const int p = blockIdx.x * blockDim.x + threadIdx.x;
    if (p >= n) return;
    const float2 xy = __ldcs(((const float2*)coord) + p);
    const int pos = atomicAdd(&g_ptr[bin_of(xy.x, xy.y)], 1);
    g_rec[pos] = make_float4(xy.x, xy.y, __int_as_float(p), 0.0f);
}

// ---------------------------------------------------------------------------
// Gather over spatially-sorted records. 4 lanes/point; corner loads via __ldg
// (L1 ON — bin locality makes corner lines reused within the block).
// Output scattered by original index (full 128B per point, sector-exact).
// ---------------------------------------------------------------------------
__global__ void __launch_bounds__(256)
gather_kernel(float* __restrict__ out, int n_points) {
    const int t   = blockIdx.x * blockDim.x + threadIdx.x;
    const int s   = t >> 2;
    const int sub = t & 3;
    if (s >= n_points) return;

    const float4 rec = __ldg(&g_rec[s]);
    const int idx = __float_as_int(rec.z);

    const float ix = (rec.x + 1.0f) * 0.5f * (float)(GW - 1);
    const float iy = (rec.y + 1.0f) * 0.5f * (float)(GH - 1);

    const float fx0 = floorf(ix);
    const float fy0 = floorf(iy);
    const float wx1 = ix - fx0;
    const float wy1 = iy - fy0;
    const float wx0 = 1.0f - wx1;
    const float wy0 = 1.0f - wy1;

    int x0 = (int)fx0; x0 = x0 < 0 ? 0 : (x0 > GW - 1 ? GW - 1 : x0);
    int y0 = (int)fy0; y0 = y0 < 0 ? 0 : (y0 > GH - 1 ? GH - 1 : y0);
    int x1 = x0 + 1;   x1 = x1 > GW - 1 ? GW - 1 : x1;
    int y1 = y0 + 1;   y1 = y1 > GH - 1 ? GH - 1 : y1;

    const float w_nw = wx0 * wy0;
    const float w_ne = wx1 * wy0;
    const float w_sw = wx0 * wy1;
    const float w_se = wx1 * wy1;

    const uint4* __restrict__ base = (const uint4*)g_params_h;
    const uint4 r_nw = __ldg(base + (((size_t)y0 << 10) + x0) * 4 + sub);
    const uint4 r_ne = __ldg(base + (((size_t)y0 << 10) + x1) * 4 + sub);
    const uint4 r_sw = __ldg(base + (((size_t)y1 << 10) + x0) * 4 + sub);
    const uint4 r_se = __ldg(base + (((size_t)y1 << 10) + x1) * 4 + sub);

    float o[8];
#pragma unroll
    for (int h = 0; h < 4; h++) {
        const unsigned ua = (&r_nw.x)[h];
        const unsigned ub = (&r_ne.x)[h];
        const unsigned uc = (&r_sw.x)[h];
        const unsigned ud = (&r_se.x)[h];
        const float2 a = __half22float2(*(const __half2*)&ua);
        const float2 b = __half22float2(*(const __half2*)&ub);
        const float2 c = __half22float2(*(const __half2*)&uc);
        const float2 d = __half22float2(*(const __half2*)&ud);
        o[2 * h + 0] = a.x * w_nw + b.x * w_ne + c.x * w_sw + d.x * w_se;
        o[2 * h + 1] = a.y * w_nw + b.y * w_ne + c.y * w_sw + d.y * w_se;
    }

    float4* __restrict__ ov = ((float4*)out) + (size_t)idx * 8 + 2 * sub;
    __stcs(ov + 0, make_float4(o[0], o[1], o[2], o[3]));
    __stcs(ov + 1, make_float4(o[4], o[5], o[6], o[7]));
}

extern "C" void kernel_launch(void* const* d_in, const int* in_sizes, int n_in,
                              void* d_out, int out_size) {
    const float* coord;
    const float* params;
    int coord_elems;
    if (in_sizes[0] < in_sizes[1]) {
        coord = (const float*)d_in[0];
        params = (const float*)d_in[1];
        coord_elems = in_sizes[0];
    } else {
        coord = (const float*)d_in[1];
        params = (const float*)d_in[0];
        coord_elems = in_sizes[1];
    }
    const int n_points = coord_elems / 2;
    const int pb = 256;
    const int pgrid = (n_points + pb - 1) / pb;

    transpose_kernel<<<GHW / 256, 256>>>(params);
    zero_hist_kernel<<<NBINS / 256, 256>>>();
    hist_kernel<<<pgrid, pb>>>(coord, n_points);
    scan_kernel<<<1, 1024>>>();
    scatter_kernel<<<pgrid, pb>>>(coord, n_points);

    const int total_threads = n_points * 4;
    const int grid = (total_threads + pb - 1) / pb;
    gather_kernel<<<grid, pb>>>((float*)d_out, n_points);
}

// round 9
// speedup vs baseline: 1.3914x; 1.3914x over previous
#include <cuda_runtime.h>
#include <cuda_fp16.h>
#include <cstddef>

#define GH 1024
#define GW 1024
#define GC 32
#define GHW (GH * GW)

// 64 MB transposed fp16 params: [HW, C], 64B per cell.
__device__ __half g_params_h[(size_t)GHW * GC];

// ---------------------------------------------------------------------------
// Kernel 1: transpose + convert, no smem. One thread = one point.
// ---------------------------------------------------------------------------
__global__ void transpose_kernel(const float* __restrict__ in) {
    const int p = blockIdx.x * blockDim.x + threadIdx.x;
    float v[32];
#pragma unroll
    for (int c = 0; c < 32; c++) v[c] = __ldcs(in + (size_t)c * GHW + p);
    uint4* __restrict__ outv = (uint4*)(g_params_h + (size_t)p * GC);
#pragma unroll
    for (int q = 0; q < 4; q++) {
        union { __half2 h2[4]; uint4 u; } pack;
#pragma unroll
        for (int j = 0; j < 4; j++)
            pack.h2[j] = __floats2half2_rn(v[q * 8 + 2 * j], v[q * 8 + 2 * j + 1]);
        outv[q] = pack.u;
    }
}

// L2-only 16B load (skip L1: near-0% hit rate on random 32-64MB working set).
__device__ __forceinline__ uint4 ldcg16(const uint4* p) {
    uint4 r;
    asm volatile("ld.global.cg.v4.u32 {%0,%1,%2,%3}, [%4];"
                 : "=r"(r.x), "=r"(r.y), "=r"(r.z), "=r"(r.w) : "l"(p));
    return r;
}

// ---------------------------------------------------------------------------
// Kernel 2: bilinear gather, phased by y-half. Each launch handles only the
// points whose y0 falls in its half of the grid -> 32MB instantaneous param
// working set (25% of L2), so the 256MB output store stream no longer evicts
// params. Structure otherwise identical to the best (R7) kernel:
// 4 lanes/point, 4x LDG.128 per point, 32 regs, high occupancy.
// ---------------------------------------------------------------------------
__global__ void __launch_bounds__(256)
gather_kernel(const float* __restrict__ coord,
              float* __restrict__ out,
              int n_points, int phase) {
    const int t   = blockIdx.x * blockDim.x + threadIdx.x;
    const int p   = t >> 2;
    const int sub = t & 3;          // 8 channels per lane
    if (p >= n_points) return;

    const float2 xy = __ldg(((const float2*)coord) + p);

    const float ix = (xy.x + 1.0f) * 0.5f * (float)(GW - 1);
    const float iy = (xy.y + 1.0f) * 0.5f * (float)(GH - 1);

    const float fx0 = floorf(ix);
    const float fy0 = floorf(iy);

    int y0 = (int)fy0; y0 = y0 < 0 ? 0 : (y0 > GH - 1 ? GH - 1 : y0);
    if ((y0 >> 9) != phase) return;   // not this phase's half

    const float wx1 = ix - fx0;
    const float wy1 = iy - fy0;
    const float wx0 = 1.0f - wx1;
    const float wy0 = 1.0f - wy1;

    int x0 = (int)fx0; x0 = x0 < 0 ? 0 : (x0 > GW - 1 ? GW - 1 : x0);
    int x1 = x0 + 1;   x1 = x1 > GW - 1 ? GW - 1 : x1;
    int y1 = y0 + 1;   y1 = y1 > GH - 1 ? GH - 1 : y1;

    const float w_nw = wx0 * wy0;
    const float w_ne = wx1 * wy0;
    const float w_sw = wx0 * wy1;
    const float w_se = wx1 * wy1;

    const uint4* __restrict__ base = (const uint4*)g_params_h;
    const uint4 r_nw = ldcg16(base + (((size_t)y0 << 10) + x0) * 4 + sub);
    const uint4 r_ne = ldcg16(base + (((size_t)y0 << 10) + x1) * 4 + sub);
    const uint4 r_sw = ldcg16(base + (((size_t)y1 << 10) + x0) * 4 + sub);
    const uint4 r_se = ldcg16(base + (((size_t)y1 << 10) + x1) * 4 + sub);

    float o[8];
#pragma unroll
    for (int h = 0; h < 4; h++) {
        const unsigned ua = (&r_nw.x)[h];
        const unsigned ub = (&r_ne.x)[h];
        const unsigned uc = (&r_sw.x)[h];
        const unsigned ud = (&r_se.x)[h];
        const float2 a = __half22float2(*(const __half2*)&ua);
        const float2 b = __half22float2(*(const __half2*)&ub);
        const float2 c = __half22float2(*(const __half2*)&uc);
        const float2 d = __half22float2(*(const __half2*)&ud);
        o[2 * h + 0] = a.x * w_nw + b.x * w_ne + c.x * w_sw + d.x * w_se;
        o[2 * h + 1] = a.y * w_nw + b.y * w_ne + c.y * w_sw + d.y * w_se;
    }

    float4* __restrict__ ov = ((float4*)out) + (size_t)p * 8 + 2 * sub;
    __stcs(ov + 0, make_float4(o[0], o[1], o[2], o[3]));
    __stcs(ov + 1, make_float4(o[4], o[5], o[6], o[7]));
}

extern "C" void kernel_launch(void* const* d_in, const int* in_sizes, int n_in,
                              void* d_out, int out_size) {
    const float* coord;
    const float* params;
    int coord_elems;
    if (in_sizes[0] < in_sizes[1]) {
        coord = (const float*)d_in[0];
        params = (const float*)d_in[1];
        coord_elems = in_sizes[0];
    } else {
        coord = (const float*)d_in[1];
        params = (const float*)d_in[0];
        coord_elems = in_sizes[1];
    }
    const int n_points = coord_elems / 2;

    transpose_kernel<<<GHW / 256, 256>>>(params);

    const int total_threads = n_points * 4;
    const int block = 256;
    const int grid = (total_threads + block - 1) / block;
    gather_kernel<<<grid, block>>>(coord, (float*)d_out, n_points, 0);
    gather_kernel<<<grid, block>>>(coord, (float*)d_out, n_points, 1);
}

// round 10
// speedup vs baseline: 1.6105x; 1.1575x over previous
#include <cuda_runtime.h>
#include <cuda_fp16.h>
#include <cstdint>
#include <cstddef>

#define GH 1024
#define GW 1024
#define GC 32
#define GHW (GH * GW)

// 64 MB transposed fp16 params: [HW, C], 64B per cell.
__device__ __half g_params_h[(size_t)GHW * GC];

// Fractional L2 policy: evict_last on hit/fill for the whole access stream.
__device__ __forceinline__ uint64_t evict_last_policy() {
    uint64_t p;
    asm("createpolicy.fractional.L2::evict_last.b64 %0, 1.0;" : "=l"(p));
    return p;
}

__device__ __forceinline__ void st16_evict_last(uint4* ptr, uint4 v, uint64_t pol) {
    asm volatile("st.global.L2::cache_hint.v4.u32 [%0], {%1,%2,%3,%4}, %5;"
                 :: "l"(ptr), "r"(v.x), "r"(v.y), "r"(v.z), "r"(v.w), "l"(pol)
                 : "memory");
}

__device__ __forceinline__ uint4 ld16_evict_last(const uint4* ptr, uint64_t pol) {
    uint4 r;
    asm volatile("ld.global.nc.L2::cache_hint.v4.u32 {%0,%1,%2,%3}, [%4], %5;"
                 : "=r"(r.x), "=r"(r.y), "=r"(r.z), "=r"(r.w)
                 : "l"(ptr), "l"(pol));
    return r;
}

// ---------------------------------------------------------------------------
// Kernel 1: transpose + convert, no smem. One thread = one point.
// Params written into L2 with evict_last priority so they survive the
// gather's 256MB output stream.
// ---------------------------------------------------------------------------
__global__ void transpose_kernel(const float* __restrict__ in) {
    const int p = blockIdx.x * blockDim.x + threadIdx.x;
    const uint64_t pol = evict_last_policy();

    float v[32];
#pragma unroll
    for (int c = 0; c < 32; c++) v[c] = __ldcs(in + (size_t)c * GHW + p);

    uint4* __restrict__ outv = (uint4*)(g_params_h + (size_t)p * GC);
#pragma unroll
    for (int q = 0; q < 4; q++) {
        union { __half2 h2[4]; uint4 u; } pack;
#pragma unroll
        for (int j = 0; j < 4; j++)
            pack.h2[j] = __floats2half2_rn(v[q * 8 + 2 * j], v[q * 8 + 2 * j + 1]);
        st16_evict_last(outv + q, pack.u, pol);
    }
}

// ---------------------------------------------------------------------------
// Kernel 2: bilinear gather (R7 structure: 4 lanes/point, 4x LDG.128,
// 32 regs, high occupancy). Param loads carry the evict_last policy; output
// stores are evict-first (.cs).
// ---------------------------------------------------------------------------
__global__ void __launch_bounds__(256)
gather_kernel(const float* __restrict__ coord,
              float* __restrict__ out,
              int n_points) {
    const int t   = blockIdx.x * blockDim.x + threadIdx.x;
    const int p   = t >> 2;
    const int sub = t & 3;          // 8 channels per lane
    if (p >= n_points) return;

    const uint64_t pol = evict_last_policy();
    const float2 xy = __ldcs(((const float2*)coord) + p);

    const float ix = (xy.x + 1.0f) * 0.5f * (float)(GW - 1);
    const float iy = (xy.y + 1.0f) * 0.5f * (float)(GH - 1);

    const float fx0 = floorf(ix);
    const float fy0 = floorf(iy);
    const float wx1 = ix - fx0;
    const float wy1 = iy - fy0;
    const float wx0 = 1.0f - wx1;
    const float wy0 = 1.0f - wy1;

    int x0 = (int)fx0; x0 = x0 < 0 ? 0 : (x0 > GW - 1 ? GW - 1 : x0);
    int y0 = (int)fy0; y0 = y0 < 0 ? 0 : (y0 > GH - 1 ? GH - 1 : y0);
    int x1 = x0 + 1;   x1 = x1 > GW - 1 ? GW - 1 : x1;
    int y1 = y0 + 1;   y1 = y1 > GH - 1 ? GH - 1 : y1;

    const float w_nw = wx0 * wy0;
    const float w_ne = wx1 * wy0;
    const float w_sw = wx0 * wy1;
    const float w_se = wx1 * wy1;

    const uint4* __restrict__ base = (const uint4*)g_params_h;
    const uint4 r_nw = ld16_evict_last(base + (((size_t)y0 << 10) + x0) * 4 + sub, pol);
    const uint4 r_ne = ld16_evict_last(base + (((size_t)y0 << 10) + x1) * 4 + sub, pol);
    const uint4 r_sw = ld16_evict_last(base + (((size_t)y1 << 10) + x0) * 4 + sub, pol);
    const uint4 r_se = ld16_evict_last(base + (((size_t)y1 << 10) + x1) * 4 + sub, pol);

    float o[8];
#pragma unroll
    for (int h = 0; h < 4; h++) {
        const unsigned ua = (&r_nw.x)[h];
        const unsigned ub = (&r_ne.x)[h];
        const unsigned uc = (&r_sw.x)[h];
        const unsigned ud = (&r_se.x)[h];
        const float2 a = __half22float2(*(const __half2*)&ua);
        const float2 b = __half22float2(*(const __half2*)&ub);
        const float2 c = __half22float2(*(const __half2*)&uc);
        const float2 d = __half22float2(*(const __half2*)&ud);
        o[2 * h + 0] = a.x * w_nw + b.x * w_ne + c.x * w_sw + d.x * w_se;
        o[2 * h + 1] = a.y * w_nw + b.y * w_ne + c.y * w_sw + d.y * w_se;
    }

    float4* __restrict__ ov = ((float4*)out) + (size_t)p * 8 + 2 * sub;
    __stcs(ov + 0, make_float4(o[0], o[1], o[2], o[3]));
    __stcs(ov + 1, make_float4(o[4], o[5], o[6], o[7]));
}

extern "C" void kernel_launch(void* const* d_in, const int* in_sizes, int n_in,
                              void* d_out, int out_size) {
    const float* coord;
    const float* params;
    int coord_elems;
    if (in_sizes[0] < in_sizes[1]) {
        coord = (const float*)d_in[0];
        params = (const float*)d_in[1];
        coord_elems = in_sizes[0];
    } else {
        coord = (const float*)d_in[1];
        params = (const float*)d_in[0];
        coord_elems = in_sizes[1];
    }
    const int n_points = coord_elems / 2;

    transpose_kernel<<<GHW / 256, 256>>>(params);

    const int total_threads = n_points * 4;
    const int block = 256;
    const int grid = (total_threads + block - 1) / block;
    gather_kernel<<<grid, block>>>(coord, (float*)d_out, n_points);
}